// round 17
// baseline (speedup 1.0000x reference)
#include <cuda_runtime.h>

// Problem constants
#define N      6144
#define GRID   148      // one block per SM
#define TP     512      // 16 warps
#define NW     16
#define MAXR   48
#define CH     4        // rows per chunk in the merged section (e-staged)

typedef unsigned long long u64;

// MUFU.EX2 forced via PTX.
__device__ __forceinline__ float ex2(float v) {
    float r;
    asm("ex2.approx.f32 %0, %1;" : "=f"(r) : "f"(v));
    return r;
}
// Packed f32x2 ops (FFMA2/FADD2/FMUL2 — only reachable via PTX).
__device__ __forceinline__ u64 pk2(float lo, float hi) {
    u64 r; asm("mov.b64 %0, {%1,%2};" : "=l"(r) : "f"(lo), "f"(hi)); return r;
}
__device__ __forceinline__ void upk2(u64 v, float& lo, float& hi) {
    asm("mov.b64 {%0,%1}, %2;" : "=f"(lo), "=f"(hi) : "l"(v));
}
__device__ __forceinline__ u64 fma2_(u64 a, u64 b, u64 c) {
    u64 r; asm("fma.rn.f32x2 %0, %1, %2, %3;" : "=l"(r) : "l"(a), "l"(b), "l"(c)); return r;
}
__device__ __forceinline__ u64 mul2_(u64 a, u64 b) {
    u64 r; asm("mul.rn.f32x2 %0, %1, %2;" : "=l"(r) : "l"(a), "l"(b)); return r;
}
__device__ __forceinline__ u64 add2_(u64 a, u64 b) {
    u64 r; asm("add.rn.f32x2 %0, %1, %2;" : "=l"(r) : "l"(a), "l"(b)); return r;
}

// Dynamic SMEM overlay (~205 KB).
struct Smem {
    u64    e[2][CH][6][TP];    // parity-buffered packed e of a matrix-1 chunk
    float4 ps[MAXR][NW + 1];   // per-warp partials (bank-padded)
    float  y2s[MAXR][3];       // (a2@v2) rows
    float  meta[CH];           // per-chunk 1/rowsum1
};

// ---------------------------------------------------------------------------
// ONE kernel, one block per SM.
//  Sec A: matrix-2 warp-autonomous packed partials -> y2s (as R16).
//  Sec B: matrix-1, interleaved j-ownership (j = 2t + 1024p). Partial pass
//    STAGES each pair's packed e through SMEM; the write pass is then just
//    LDS.64 -> FMUL2 -> STG.64 (no logit/EX2 recompute -> EX2 count drops
//    from 3N^2 to 2N^2 and write issue content ~halves). Parity e-buffers
//    keep the write(c-1) || partial(c) overlap with 2 barriers per chunk.
// ---------------------------------------------------------------------------
__global__ void __launch_bounds__(TP, 1) fused_kernel(
    const float* __restrict__ x,
    const float* __restrict__ wq1, const float* __restrict__ bq1,
    const float* __restrict__ wq2, const float* __restrict__ bq2,
    const float* __restrict__ wq3, const float* __restrict__ bq3,
    const float* __restrict__ wq4, const float* __restrict__ bq4,
    const float* __restrict__ wk1, const float* __restrict__ bk1,
    const float* __restrict__ wk2, const float* __restrict__ bk2,
    const float* __restrict__ wv1, const float* __restrict__ bv1,
    const float* __restrict__ wv2, const float* __restrict__ bv2,
    const float* __restrict__ wb,  const float* __restrict__ bb,
    float* __restrict__ a_out,     // [N, N]
    float* __restrict__ b_out)     // [N, 3]
{
    extern __shared__ char raw[];
    Smem& sm = *reinterpret_cast<Smem*>(raw);

    const int t  = threadIdx.x;
    const int w  = t >> 5;
    const int l  = t & 31;
    const int r0 = (int)(((long long)N * blockIdx.x) / GRID);
    const int r1 = (int)(((long long)N * (blockIdx.x + 1)) / GRID);
    const int nr = r1 - r0;
    const float LOG2E = 1.4426950408889634f;

    u64 kxp[6], kyp[6], kzp[6], vxp[6], vyp[6], vzp[6];

    // =======================================================================
    // Sec A: matrix 2 (g=q3+q4, k2, v2) -> y2s
    // =======================================================================
    {
        float wg[9], bg[3];
        #pragma unroll
        for (int c = 0; c < 3; c++) {
            wg[c*3+0] = (wq3[c*3+0] + wq4[c*3+0]) * LOG2E;
            wg[c*3+1] = (wq3[c*3+1] + wq4[c*3+1]) * LOG2E;
            wg[c*3+2] = (wq3[c*3+2] + wq4[c*3+2]) * LOG2E;
            bg[c]     = (bq3[c] + bq4[c]) * LOG2E;
        }
        {   // packed K2/V2, contiguous j slice (j0 = 12t), float4 x loads
            float xs[36];
            const float4* xp = (const float4*)(x + 36 * t);
            #pragma unroll
            for (int q = 0; q < 9; q++) {
                float4 f = xp[q];
                xs[4*q] = f.x; xs[4*q+1] = f.y; xs[4*q+2] = f.z; xs[4*q+3] = f.w;
            }
            #pragma unroll
            for (int p = 0; p < 6; p++) {
                float X0 = xs[6*p+0], X1 = xs[6*p+1], X2 = xs[6*p+2];
                float Y0 = xs[6*p+3], Y1 = xs[6*p+4], Y2 = xs[6*p+5];
                kxp[p] = pk2(bk2[0] + wk2[0]*X0 + wk2[1]*X1 + wk2[2]*X2,
                             bk2[0] + wk2[0]*Y0 + wk2[1]*Y1 + wk2[2]*Y2);
                kyp[p] = pk2(bk2[1] + wk2[3]*X0 + wk2[4]*X1 + wk2[5]*X2,
                             bk2[1] + wk2[3]*Y0 + wk2[4]*Y1 + wk2[5]*Y2);
                kzp[p] = pk2(bk2[2] + wk2[6]*X0 + wk2[7]*X1 + wk2[8]*X2,
                             bk2[2] + wk2[6]*Y0 + wk2[7]*Y1 + wk2[8]*Y2);
                vxp[p] = pk2(bv2[0] + wv2[0]*X0 + wv2[1]*X1 + wv2[2]*X2,
                             bv2[0] + wv2[0]*Y0 + wv2[1]*Y1 + wv2[2]*Y2);
                vyp[p] = pk2(bv2[1] + wv2[3]*X0 + wv2[4]*X1 + wv2[5]*X2,
                             bv2[1] + wv2[3]*Y0 + wv2[4]*Y1 + wv2[5]*Y2);
                vzp[p] = pk2(bv2[2] + wv2[6]*X0 + wv2[7]*X1 + wv2[8]*X2,
                             bv2[2] + wv2[6]*Y0 + wv2[7]*Y1 + wv2[8]*Y2);
            }
        }
        for (int i = r0; i < r1; i++) {
            float X0 = __ldg(x + 3*i), X1 = __ldg(x + 3*i + 1), X2 = __ldg(x + 3*i + 2);
            float gxs = bg[0] + wg[0]*X0 + wg[1]*X1 + wg[2]*X2;
            float gys = bg[1] + wg[3]*X0 + wg[4]*X1 + wg[5]*X2;
            float gzs = bg[2] + wg[6]*X0 + wg[7]*X1 + wg[8]*X2;
            u64 gx = pk2(gxs, gxs), gy = pk2(gys, gys), gz = pk2(gzs, gzs);

            u64 sum = 0, ax = 0, ay = 0, az = 0;
            #pragma unroll
            for (int p = 0; p < 6; p++) {
                u64 lg = fma2_(gx, kxp[p], fma2_(gy, kyp[p], mul2_(gz, kzp[p])));
                float l0, l1;  upk2(lg, l0, l1);
                u64 e2 = pk2(ex2(l0), ex2(l1));
                sum = add2_(sum, e2);
                ax  = fma2_(e2, vxp[p], ax);
                ay  = fma2_(e2, vyp[p], ay);
                az  = fma2_(e2, vzp[p], az);
            }
            float r0a, r1a, r2a, r3a, hi;
            upk2(sum, r0a, hi); r0a += hi;
            upk2(ax,  r1a, hi); r1a += hi;
            upk2(ay,  r2a, hi); r2a += hi;
            upk2(az,  r3a, hi); r3a += hi;
            #pragma unroll
            for (int o = 16; o > 0; o >>= 1) {
                r0a += __shfl_xor_sync(0xffffffffu, r0a, o);
                r1a += __shfl_xor_sync(0xffffffffu, r1a, o);
                r2a += __shfl_xor_sync(0xffffffffu, r2a, o);
                r3a += __shfl_xor_sync(0xffffffffu, r3a, o);
            }
            if (l == 0) {
                float4 p4; p4.x = r0a; p4.y = r1a; p4.z = r2a; p4.w = r3a;
                sm.ps[i - r0][w] = p4;
            }
        }
    }
    __syncthreads();
    if (t < nr) {
        float s2 = 0.f, a2x = 0.f, a2y = 0.f, a2z = 0.f;
        #pragma unroll
        for (int ww = 0; ww < NW; ww++) {
            float4 p = sm.ps[t][ww];
            s2 += p.x; a2x += p.y; a2y += p.z; a2z += p.w;
        }
        float inv2 = 1.0f / s2;
        sm.y2s[t][0] = a2x * inv2;
        sm.y2s[t][1] = a2y * inv2;
        sm.y2s[t][2] = a2z * inv2;
    }
    __syncthreads();   // ps reusable, y2s visible

    // =======================================================================
    // Sec B: matrix 1, interleaved ownership j = 2t + 1024p (+{0,1}).
    // =======================================================================
    float wg1[9], bg1[3];
    #pragma unroll
    for (int c = 0; c < 3; c++) {
        wg1[c*3+0] = (wq1[c*3+0] + wq2[c*3+0]) * LOG2E;
        wg1[c*3+1] = (wq1[c*3+1] + wq2[c*3+1]) * LOG2E;
        wg1[c*3+2] = (wq1[c*3+2] + wq2[c*3+2]) * LOG2E;
        bg1[c]     = (bq1[c] + bq2[c]) * LOG2E;
    }
    #pragma unroll
    for (int p = 0; p < 6; p++) {
        int j = 2 * t + p * 1024;       // pair (j, j+1); 3j even -> float2 ok
        const float2* xp = (const float2*)(x + 3 * j);
        float2 f0 = xp[0], f1 = xp[1], f2 = xp[2];
        float X0 = f0.x, X1 = f0.y, X2 = f1.x;
        float Y0 = f1.y, Y1 = f2.x, Y2 = f2.y;
        kxp[p] = pk2(bk1[0] + wk1[0]*X0 + wk1[1]*X1 + wk1[2]*X2,
                     bk1[0] + wk1[0]*Y0 + wk1[1]*Y1 + wk1[2]*Y2);
        kyp[p] = pk2(bk1[1] + wk1[3]*X0 + wk1[4]*X1 + wk1[5]*X2,
                     bk1[1] + wk1[3]*Y0 + wk1[4]*Y1 + wk1[5]*Y2);
        kzp[p] = pk2(bk1[2] + wk1[6]*X0 + wk1[7]*X1 + wk1[8]*X2,
                     bk1[2] + wk1[6]*Y0 + wk1[7]*Y1 + wk1[8]*Y2);
        vxp[p] = pk2(bv1[0] + wv1[0]*X0 + wv1[1]*X1 + wv1[2]*X2,
                     bv1[0] + wv1[0]*Y0 + wv1[1]*Y1 + wv1[2]*Y2);
        vyp[p] = pk2(bv1[1] + wv1[3]*X0 + wv1[4]*X1 + wv1[5]*X2,
                     bv1[1] + wv1[3]*Y0 + wv1[4]*Y1 + wv1[5]*Y2);
        vzp[p] = pk2(bv1[2] + wv1[6]*X0 + wv1[7]*X1 + wv1[8]*X2,
                     bv1[2] + wv1[6]*Y0 + wv1[7]*Y1 + wv1[8]*Y2);
    }

    const int nch = (nr + CH - 1) / CH;

    // --- partial chunk: compute e, STAGE it to smem, accumulate partials ---
    #define PARTIAL_CHUNK(c)                                                    \
    {                                                                           \
        const int par = (c) & 1;                                                \
        for (int r = 0; r < CH; r++) {                                          \
            int i = r0 + (c) * CH + r;                                          \
            if (i >= r1) break;                                                 \
            float X0 = __ldg(x + 3*i), X1 = __ldg(x + 3*i + 1), X2 = __ldg(x + 3*i + 2); \
            float gxs = bg1[0] + wg1[0]*X0 + wg1[1]*X1 + wg1[2]*X2;             \
            float gys = bg1[1] + wg1[3]*X0 + wg1[4]*X1 + wg1[5]*X2;             \
            float gzs = bg1[2] + wg1[6]*X0 + wg1[7]*X1 + wg1[8]*X2;             \
            u64 gx = pk2(gxs, gxs), gy = pk2(gys, gys), gz = pk2(gzs, gzs);     \
            u64 sum = 0, ax = 0, ay = 0, az = 0;                                \
            _Pragma("unroll")                                                   \
            for (int p = 0; p < 6; p++) {                                       \
                u64 lg = fma2_(gx, kxp[p], fma2_(gy, kyp[p], mul2_(gz, kzp[p]))); \
                float l0, l1;  upk2(lg, l0, l1);                                \
                u64 e2 = pk2(ex2(l0), ex2(l1));                                 \
                sm.e[par][r][p][t] = e2;                                        \
                sum = add2_(sum, e2);                                           \
                ax  = fma2_(e2, vxp[p], ax);                                    \
                ay  = fma2_(e2, vyp[p], ay);                                    \
                az  = fma2_(e2, vzp[p], az);                                    \
            }                                                                   \
            float r0a, r1a, r2a, r3a, hi;                                       \
            upk2(sum, r0a, hi); r0a += hi;                                      \
            upk2(ax,  r1a, hi); r1a += hi;                                      \
            upk2(ay,  r2a, hi); r2a += hi;                                      \
            upk2(az,  r3a, hi); r3a += hi;                                      \
            _Pragma("unroll")                                                   \
            for (int o = 16; o > 0; o >>= 1) {                                  \
                r0a += __shfl_xor_sync(0xffffffffu, r0a, o);                    \
                r1a += __shfl_xor_sync(0xffffffffu, r1a, o);                    \
                r2a += __shfl_xor_sync(0xffffffffu, r2a, o);                    \
                r3a += __shfl_xor_sync(0xffffffffu, r3a, o);                    \
            }                                                                   \
            if (l == 0) {                                                       \
                float4 p4; p4.x = r0a; p4.y = r1a; p4.z = r2a; p4.w = r3a;      \
                sm.ps[r][w] = p4;                                               \
            }                                                                   \
        }                                                                       \
    }

    // --- chunk combine: inv1 + fused b_out ---
    #define COMBINE_CHUNK(c)                                                    \
    if (t < CH && (c) * CH + t < nr) {                                          \
        int i = r0 + (c) * CH + t;                                              \
        float s1 = 0.f, a1x = 0.f, a1y = 0.f, a1z = 0.f;                        \
        _Pragma("unroll")                                                       \
        for (int ww = 0; ww < NW; ww++) {                                       \
            float4 p = sm.ps[t][ww];                                            \
            s1 += p.x; a1x += p.y; a1y += p.z; a1z += p.w;                      \
        }                                                                       \
        float inv1 = 1.0f / s1;                                                 \
        sm.meta[t] = inv1;                                                      \
        int lr = (c) * CH + t;                                                  \
        float y0 = a1x * inv1 + sm.y2s[lr][0];                                  \
        float y1 = a1y * inv1 + sm.y2s[lr][1];                                  \
        float yz = a1z * inv1 + sm.y2s[lr][2];                                  \
        _Pragma("unroll")                                                       \
        for (int cc = 0; cc < 3; cc++)                                          \
            b_out[i*3+cc] = bb[cc] + wb[cc*3+0]*y0 + wb[cc*3+1]*y1 + wb[cc*3+2]*yz; \
    }

    // --- chunk writes: LDS staged e -> scale -> coalesced STG.64 ---
    #define WRITE_CHUNK(c)                                                      \
    {                                                                           \
        const int par = (c) & 1;                                                \
        for (int r = 0; r < CH; r++) {                                          \
            int i = r0 + (c) * CH + r;                                          \
            if (i >= r1) break;                                                 \
            float inv = sm.meta[r];                                             \
            u64 iv2 = pk2(inv, inv);                                            \
            float* rowp = a_out + (size_t)i * N + 2 * t;                        \
            _Pragma("unroll")                                                   \
            for (int p = 0; p < 6; p++) {                                       \
                u64 o2 = mul2_(sm.e[par][r][p][t], iv2);                        \
                float2 o;  upk2(o2, o.x, o.y);                                  \
                __stcs((float2*)(rowp + p * 1024), o);                          \
            }                                                                   \
        }                                                                       \
    }

    PARTIAL_CHUNK(0)
    __syncthreads();
    COMBINE_CHUNK(0)
    __syncthreads();
    for (int c = 1; c < nch; c++) {
        WRITE_CHUNK(c - 1)      // reads e[par^1] + meta(c-1), overlaps with...
        PARTIAL_CHUNK(c)        // ...e[par] fills + partial math
        __syncthreads();
        COMBINE_CHUNK(c)
        __syncthreads();
    }
    WRITE_CHUNK(nch - 1)

    #undef PARTIAL_CHUNK
    #undef COMBINE_CHUNK
    #undef WRITE_CHUNK
}

// ---------------------------------------------------------------------------
// ONE launch. Output layout: a1 [N*N] followed by b [N*3].
// ---------------------------------------------------------------------------
extern "C" void kernel_launch(void* const* d_in, const int* in_sizes, int n_in,
                              void* d_out, int out_size)
{
    const float* x   = (const float*)d_in[0];
    const float* wq1 = (const float*)d_in[1];
    const float* bq1 = (const float*)d_in[2];
    const float* wq2 = (const float*)d_in[3];
    const float* bq2 = (const float*)d_in[4];
    const float* wq3 = (const float*)d_in[5];
    const float* bq3 = (const float*)d_in[6];
    const float* wq4 = (const float*)d_in[7];
    const float* bq4 = (const float*)d_in[8];
    const float* wk1 = (const float*)d_in[9];
    const float* bk1 = (const float*)d_in[10];
    const float* wk2 = (const float*)d_in[11];
    const float* bk2 = (const float*)d_in[12];
    const float* wv1 = (const float*)d_in[13];
    const float* bv1 = (const float*)d_in[14];
    const float* wv2 = (const float*)d_in[15];
    const float* bv2 = (const float*)d_in[16];
    const float* wb  = (const float*)d_in[17];
    const float* bb  = (const float*)d_in[18];

    float* out = (float*)d_out;
    float* a1  = out;                      // [N, N]
    float* b   = out + (size_t)N * N;      // [N, 3]

    // Host-side attribute set (immediate, not captured) for >48KB dynamic SMEM.
    cudaFuncSetAttribute(fused_kernel,
                         cudaFuncAttributeMaxDynamicSharedMemorySize,
                         (int)sizeof(Smem));

    fused_kernel<<<GRID, TP, sizeof(Smem)>>>(
        x, wq1, bq1, wq2, bq2, wq3, bq3, wq4, bq4,
        wk1, bk1, wk2, bk2, wv1, bv1, wv2, bv2,
        wb, bb, a1, b);
}